// round 12
// baseline (speedup 1.0000x reference)
#include <cuda_runtime.h>
#include <cuda_bf16.h>

#define N_NODES 50000
#define D_FEAT  128
#define FULL 0xffffffffu

// Fused single kernel: one warp per node. The warp finds its edge range
// [beg, end) by dual binary search over the sorted edge_src (all lanes run
// the identical search -> broadcast loads, 1 sector/step), then does the
// unroll-4 __ldcg row-gather accumulation (the measured-floor body).
__global__ void __launch_bounds__(64)
graph_pool_fused_kernel(const float4* __restrict__ x,
                        const int* __restrict__ edge_src,
                        const int* __restrict__ edge_dst,
                        float4* __restrict__ out,
                        int n_edges) {
    int warp_id = (blockIdx.x * blockDim.x + threadIdx.x) >> 5;
    int lane = threadIdx.x & 31;
    if (warp_id >= N_NODES) return;

    // self feature first: its latency overlaps the binary search
    float4 acc = x[(size_t)warp_id * 32 + lane];

    // dual lower_bound: beg = lb(warp_id), end = lb(warp_id + 1)
    // two independent chains interleaved for ILP=2.
    int key0 = warp_id;
    int key1 = warp_id + 1;
    int lo0 = 0, hi0 = n_edges;
    int lo1 = 0, hi1 = n_edges;
    while (lo0 < hi0 || lo1 < hi1) {
        int m0 = (lo0 + hi0) >> 1;
        int m1 = (lo1 + hi1) >> 1;
        int v0 = 0, v1 = 0;
        if (lo0 < hi0) v0 = __ldg(&edge_src[m0]);
        if (lo1 < hi1) v1 = __ldg(&edge_src[m1]);
        if (lo0 < hi0) { if (v0 < key0) lo0 = m0 + 1; else hi0 = m0; }
        if (lo1 < hi1) { if (v1 < key1) lo1 = m1 + 1; else hi1 = m1; }
    }
    int beg = lo0;
    int end = lo1;

    int e = beg;
    for (; e + 4 <= end; e += 4) {
        int d0 = edge_dst[e + 0];
        int d1 = edge_dst[e + 1];
        int d2 = edge_dst[e + 2];
        int d3 = edge_dst[e + 3];
        float4 v0 = __ldcg(&x[(size_t)d0 * 32 + lane]);
        float4 v1 = __ldcg(&x[(size_t)d1 * 32 + lane]);
        float4 v2 = __ldcg(&x[(size_t)d2 * 32 + lane]);
        float4 v3 = __ldcg(&x[(size_t)d3 * 32 + lane]);
        acc.x += v0.x; acc.y += v0.y; acc.z += v0.z; acc.w += v0.w;
        acc.x += v1.x; acc.y += v1.y; acc.z += v1.z; acc.w += v1.w;
        acc.x += v2.x; acc.y += v2.y; acc.z += v2.z; acc.w += v2.w;
        acc.x += v3.x; acc.y += v3.y; acc.z += v3.z; acc.w += v3.w;
    }
    for (; e < end; e++) {
        int d = edge_dst[e];
        float4 v = __ldcg(&x[(size_t)d * 32 + lane]);
        acc.x += v.x; acc.y += v.y; acc.z += v.z; acc.w += v.w;
    }

    __stcg(&out[(size_t)warp_id * 32 + lane], acc);
}

extern "C" void kernel_launch(void* const* d_in, const int* in_sizes, int n_in,
                              void* d_out, int out_size) {
    const float* x = (const float*)d_in[0];
    const int* edge_src = (const int*)d_in[1];
    const int* edge_dst = (const int*)d_in[2];
    float* out = (float*)d_out;
    int n_edges = in_sizes[1];

    int threads = 64;  // 2 warps per block
    int warps_per_block = threads / 32;
    int blocks = (N_NODES + warps_per_block - 1) / warps_per_block;
    graph_pool_fused_kernel<<<blocks, threads>>>((const float4*)x, edge_src,
                                                 edge_dst, (float4*)out,
                                                 n_edges);
}

// round 13
// speedup vs baseline: 1.7719x; 1.7719x over previous
#include <cuda_runtime.h>
#include <cuda_bf16.h>

#define N_NODES 50000
#define D_FEAT  128

// CSR row offsets into the sorted edge list. 50001 ints.
__device__ int g_offsets[N_NODES + 1];

// Kernel A: boundary-diff scatter, 4 edges per thread via int4.
__global__ void build_offsets_kernel(const int* __restrict__ edge_src, int n_edges) {
    int t = blockIdx.x * blockDim.x + threadIdx.x;
    int e0 = t * 4;
    if (e0 >= n_edges) return;
    int4 s = *reinterpret_cast<const int4*>(edge_src + e0);  // n_edges % 4 == 0
    int prev = (e0 == 0) ? -1 : edge_src[e0 - 1];
    for (int n = prev + 1; n <= s.x; n++) g_offsets[n] = e0;
    for (int n = s.x + 1; n <= s.y; n++) g_offsets[n] = e0 + 1;
    for (int n = s.y + 1; n <= s.z; n++) g_offsets[n] = e0 + 2;
    for (int n = s.z + 1; n <= s.w; n++) g_offsets[n] = e0 + 3;
    if (e0 + 4 >= n_edges) {
        for (int n = s.w + 1; n <= N_NODES; n++) g_offsets[n] = n_edges;
    }
}

// Kernel B: one warp per node, unroll-4 __ldcg row gathers (L2-direct),
// __stcg store. Launched with PDL: the self-row load runs before
// cudaGridDependencySynchronize(), overlapping kernel A's tail + launch gap.
__global__ void __launch_bounds__(64)
graph_pool_kernel(const float4* __restrict__ x,
                  const int* __restrict__ edge_dst,
                  float4* __restrict__ out) {
    int warp_id = (blockIdx.x * blockDim.x + threadIdx.x) >> 5;
    int lane = threadIdx.x & 31;
    if (warp_id >= N_NODES) return;

    // Pre-dependency work: self feature row (independent of g_offsets).
    float4 acc = x[(size_t)warp_id * 32 + lane];

    // Gate on kernel A's completion (PDL).
    cudaGridDependencySynchronize();

    int beg = g_offsets[warp_id];
    int end = g_offsets[warp_id + 1];

    int e = beg;
    for (; e + 4 <= end; e += 4) {
        int d0 = edge_dst[e + 0];
        int d1 = edge_dst[e + 1];
        int d2 = edge_dst[e + 2];
        int d3 = edge_dst[e + 3];
        float4 v0 = __ldcg(&x[(size_t)d0 * 32 + lane]);
        float4 v1 = __ldcg(&x[(size_t)d1 * 32 + lane]);
        float4 v2 = __ldcg(&x[(size_t)d2 * 32 + lane]);
        float4 v3 = __ldcg(&x[(size_t)d3 * 32 + lane]);
        acc.x += v0.x; acc.y += v0.y; acc.z += v0.z; acc.w += v0.w;
        acc.x += v1.x; acc.y += v1.y; acc.z += v1.z; acc.w += v1.w;
        acc.x += v2.x; acc.y += v2.y; acc.z += v2.z; acc.w += v2.w;
        acc.x += v3.x; acc.y += v3.y; acc.z += v3.z; acc.w += v3.w;
    }
    for (; e < end; e++) {
        int d = edge_dst[e];
        float4 v = __ldcg(&x[(size_t)d * 32 + lane]);
        acc.x += v.x; acc.y += v.y; acc.z += v.z; acc.w += v.w;
    }

    __stcg(&out[(size_t)warp_id * 32 + lane], acc);
}

extern "C" void kernel_launch(void* const* d_in, const int* in_sizes, int n_in,
                              void* d_out, int out_size) {
    const float* x = (const float*)d_in[0];
    const int* edge_src = (const int*)d_in[1];
    const int* edge_dst = (const int*)d_in[2];
    float* out = (float*)d_out;
    int n_edges = in_sizes[1];

    // Kernel A: O(E) boundary-diff offsets, 4 edges/thread
    {
        int threads = 256;
        int work = (n_edges + 3) / 4;
        int blocks = (work + threads - 1) / threads;
        build_offsets_kernel<<<blocks, threads>>>(edge_src, n_edges);
    }

    // Kernel B: one warp per node, 2 warps per block, PDL overlap with A
    {
        int threads = 64;
        int warps_per_block = threads / 32;
        int blocks = (N_NODES + warps_per_block - 1) / warps_per_block;

        cudaLaunchConfig_t cfg = {};
        cfg.gridDim = dim3(blocks, 1, 1);
        cfg.blockDim = dim3(threads, 1, 1);
        cfg.dynamicSmemBytes = 0;
        cfg.stream = 0;  // legacy default stream (same as <<<>>> above)

        cudaLaunchAttribute attr[1];
        attr[0].id = cudaLaunchAttributeProgrammaticStreamSerialization;
        attr[0].val.programmaticStreamSerializationAllowed = 1;
        cfg.attrs = attr;
        cfg.numAttrs = 1;

        cudaLaunchKernelEx(&cfg, graph_pool_kernel,
                           (const float4*)x, edge_dst, (float4*)out);
    }
}